// round 2
// baseline (speedup 1.0000x reference)
#include <cuda_runtime.h>

// IF neuron multi-step scan, hard reset:
//   h_t = x_t + v_{t-1};  s_t = (h_t >= 1) ? 1 : 0;  v_t = s_t ? 0 : h_t
//
// R2: each thread owns TWO float4 streams (i and i + n4/2), both coalesced.
// Combined with unroll-4 this front-batches 8 independent LDG.128 per thread
// (MLP ~8) to hide the ~577cyc DRAM latency. Streaming hints (__ldcs/__stcs)
// because every byte is touched exactly once.

__device__ __forceinline__ float4 if_step(float4 xv, float4& v)
{
    float h0 = xv.x + v.x;
    float h1 = xv.y + v.y;
    float h2 = xv.z + v.z;
    float h3 = xv.w + v.w;

    float4 s;
    s.x = (h0 >= 1.0f) ? 1.0f : 0.0f;
    s.y = (h1 >= 1.0f) ? 1.0f : 0.0f;
    s.z = (h2 >= 1.0f) ? 1.0f : 0.0f;
    s.w = (h3 >= 1.0f) ? 1.0f : 0.0f;

    v.x = (h0 >= 1.0f) ? 0.0f : h0;
    v.y = (h1 >= 1.0f) ? 0.0f : h1;
    v.z = (h2 >= 1.0f) ? 0.0f : h2;
    v.w = (h3 >= 1.0f) ? 0.0f : h3;
    return s;
}

__global__ __launch_bounds__(256) void if_scan_kernel2(
    const float4* __restrict__ x,   // [T, n4]
    const float4* __restrict__ v0,  // [n4]
    float4* __restrict__ out,       // [T, n4]
    int n4, int T)
{
    int i = blockIdx.x * blockDim.x + threadIdx.x;
    int half = n4 >> 1;
    if (i >= half) return;
    int j = i + half;

    float4 va = v0[i];
    float4 vb = v0[j];

    const float4* xa_p = x + i;
    const float4* xb_p = x + j;
    float4* oa_p = out + i;
    float4* ob_p = out + j;

    #pragma unroll 4
    for (int t = 0; t < T; ++t) {
        float4 xa = __ldcs(xa_p); xa_p += n4;
        float4 xb = __ldcs(xb_p); xb_p += n4;

        float4 sa = if_step(xa, va);
        float4 sb = if_step(xb, vb);

        __stcs(oa_p, sa); oa_p += n4;
        __stcs(ob_p, sb); ob_p += n4;
    }
}

// Fallback (n4 odd — not hit for this problem's shape, kept for safety).
__global__ __launch_bounds__(256) void if_scan_kernel1(
    const float4* __restrict__ x,
    const float4* __restrict__ v0,
    float4* __restrict__ out,
    int n4, int T)
{
    int i = blockIdx.x * blockDim.x + threadIdx.x;
    if (i >= n4) return;

    float4 v = v0[i];
    const float4* xp = x + i;
    float4* op = out + i;

    #pragma unroll 4
    for (int t = 0; t < T; ++t) {
        float4 xv = __ldcs(xp); xp += n4;
        float4 s = if_step(xv, v);
        __stcs(op, s); op += n4;
    }
}

extern "C" void kernel_launch(void* const* d_in, const int* in_sizes, int n_in,
                              void* d_out, int out_size)
{
    const float* x_seq  = (const float*)d_in[0];   // [T, B, D]
    const float* v_init = (const float*)d_in[1];   // [B, D]

    int N = in_sizes[1];              // B * D
    int T = in_sizes[0] / N;          // timesteps
    int n4 = N / 4;                   // float4 count per timestep

    int block = 256;

    if ((n4 & 1) == 0) {
        int half = n4 >> 1;
        int grid = (half + block - 1) / block;
        if_scan_kernel2<<<grid, block>>>(
            (const float4*)x_seq, (const float4*)v_init,
            (float4*)d_out, n4, T);
    } else {
        int grid = (n4 + block - 1) / block;
        if_scan_kernel1<<<grid, block>>>(
            (const float4*)x_seq, (const float4*)v_init,
            (float4*)d_out, n4, T);
    }
}

// round 3
// speedup vs baseline: 1.0859x; 1.0859x over previous
#include <cuda_runtime.h>

// IF neuron multi-step scan, hard reset:
//   h_t = x_t + v_{t-1};  s_t = (h_t >= 1) ? 1 : 0;  v_t = s_t ? 0 : h_t
//
// R3: one thread per float4 lane (full 262k threads, single wave), T-loop in
// batches of 4 with explicit double-buffered prefetch:
//   - 4 independent LDG.128 issued back-to-back (read burst)
//   - then 4 STG.128 back-to-back for the previous batch (write burst)
// keeps ~8 loads in flight per thread and groups DRAM traffic by direction.

__device__ __forceinline__ float4 if_step(float4 xv, float4& v)
{
    float h0 = xv.x + v.x;
    float h1 = xv.y + v.y;
    float h2 = xv.z + v.z;
    float h3 = xv.w + v.w;

    float4 s;
    s.x = (h0 >= 1.0f) ? 1.0f : 0.0f;
    s.y = (h1 >= 1.0f) ? 1.0f : 0.0f;
    s.z = (h2 >= 1.0f) ? 1.0f : 0.0f;
    s.w = (h3 >= 1.0f) ? 1.0f : 0.0f;

    v.x = (h0 >= 1.0f) ? 0.0f : h0;
    v.y = (h1 >= 1.0f) ? 0.0f : h1;
    v.z = (h2 >= 1.0f) ? 0.0f : h2;
    v.w = (h3 >= 1.0f) ? 0.0f : h3;
    return s;
}

// T must be a multiple of 4 (T=32 for this problem).
__global__ __launch_bounds__(256) void if_scan_b4(
    const float4* __restrict__ x,   // [T, n4]
    const float4* __restrict__ v0,  // [n4]
    float4* __restrict__ out,       // [T, n4]
    int n4, int T)
{
    int i = blockIdx.x * blockDim.x + threadIdx.x;
    if (i >= n4) return;

    float4 v = v0[i];
    const float4* xp = x + i;
    float4* op = out + i;

    long long stride = n4;

    // prologue: load batch 0
    float4 buf[4];
    #pragma unroll
    for (int k = 0; k < 4; ++k)
        buf[k] = __ldcs(xp + (long long)k * stride);
    xp += 4 * stride;

    for (int t = 4; t < T; t += 4) {
        // prefetch next batch (4 independent loads in flight)
        float4 nxt[4];
        #pragma unroll
        for (int k = 0; k < 4; ++k)
            nxt[k] = __ldcs(xp + (long long)k * stride);
        xp += 4 * stride;

        // compute + store current batch as a write burst
        #pragma unroll
        for (int k = 0; k < 4; ++k) {
            float4 s = if_step(buf[k], v);
            __stcs(op, s);
            op += stride;
        }

        #pragma unroll
        for (int k = 0; k < 4; ++k) buf[k] = nxt[k];
    }

    // epilogue: last batch
    #pragma unroll
    for (int k = 0; k < 4; ++k) {
        float4 s = if_step(buf[k], v);
        __stcs(op, s);
        op += stride;
    }
}

// Generic fallback for T not divisible by 4 (not hit for this shape).
__global__ __launch_bounds__(256) void if_scan_plain(
    const float4* __restrict__ x,
    const float4* __restrict__ v0,
    float4* __restrict__ out,
    int n4, int T)
{
    int i = blockIdx.x * blockDim.x + threadIdx.x;
    if (i >= n4) return;

    float4 v = v0[i];
    const float4* xp = x + i;
    float4* op = out + i;

    for (int t = 0; t < T; ++t) {
        float4 xv = __ldcs(xp); xp += n4;
        float4 s = if_step(xv, v);
        __stcs(op, s); op += n4;
    }
}

extern "C" void kernel_launch(void* const* d_in, const int* in_sizes, int n_in,
                              void* d_out, int out_size)
{
    const float* x_seq  = (const float*)d_in[0];   // [T, B, D]
    const float* v_init = (const float*)d_in[1];   // [B, D]

    int N = in_sizes[1];              // B * D
    int T = in_sizes[0] / N;          // timesteps
    int n4 = N / 4;

    int block = 256;
    int grid = (n4 + block - 1) / block;

    if ((T & 3) == 0) {
        if_scan_b4<<<grid, block>>>(
            (const float4*)x_seq, (const float4*)v_init,
            (float4*)d_out, n4, T);
    } else {
        if_scan_plain<<<grid, block>>>(
            (const float4*)x_seq, (const float4*)v_init,
            (float4*)d_out, n4, T);
    }
}